// round 7
// baseline (speedup 1.0000x reference)
#include <cuda_runtime.h>
#include <cstdint>

// Problem constants
#define Bb   16
#define Nn   4096
#define Dd   1024
#define Hh   512
#define Cc   4
#define Ss   64                  // chunks per bag
#define ROWS 64                  // rows per chunk (Nn/Ss)
#define TPB  256
#define NCH  (Bb * Ss)           // 1024 chunk CTAs
#define WCB  384                 // Wc CTAs (8 W1-rows each) -- run FIRST
#define TR   2                   // rows per tile
#define NT   (ROWS / TR)         // 32 tiles per chunk
#define STAGES 4                 // ring depth: 4 x 8KB = 32KB dyn smem
#define KSL  6                   // k2 slices per bag

// ---------------- scratch (static device arrays; no cudaMalloc) -------------
__device__ float g_Pm[NCH];
__device__ float g_Pl[NCH];
__device__ float g_Pacc[NCH][Dd];
__device__ float g_Psum[NCH][Dd];
__device__ float g_Pmx[NCH][Dd];
__device__ float g_Wc[3 * Dd][Cc];     // W1 @ W2 (head is affine: no activation)

__device__ __forceinline__ void cp16(uint32_t smem_dst, const float* gsrc) {
    asm volatile("cp.async.cg.shared.global [%0], [%1], 16;\n"
                 :: "r"(smem_dst), "l"(gsrc));
}
__device__ __forceinline__ void cp_commit() {
    asm volatile("cp.async.commit_group;\n");
}
template <int N> __device__ __forceinline__ void cp_wait() {
    asm volatile("cp.async.wait_group %0;\n" :: "n"(N));
}

// ============================================================================
// K1: fused [Wc = W1 @ W2] (blocks 0..WCB) + [pass1 pooling] (blocks WCB..)
//   pass1 KEY: each thread's ring slots are THREAD-PRIVATE (it cp.asyncs and
//   reads only [row*Dd + tid*4 .. +4)). So tile visibility needs only the
//   per-thread cp.async.wait_group — no block barrier — and buffer reuse has
//   no WAR hazard. The ONLY block sync is the score table sd (double-buffered)
//   => exactly 1 __syncthreads per 2-row tile.
// ============================================================================
extern __shared__ float dyn[];   // [STAGES][TR][Dd] = 32768 B (pass1) / sW2 (Wc)

__global__ __launch_bounds__(TPB, 4) void k1_kernel(
    const float* __restrict__ bags, const float* __restrict__ query,
    const float* __restrict__ W1,   const float* __restrict__ W2,
    float* __restrict__ out)
{
    const int blk = blockIdx.x;
    const int tid = threadIdx.x;

    if (blk < WCB) {
        // block 0 also zero-inits out (k2 accumulates into it atomically)
        if (blk == 0 && tid < Bb * Cc) out[tid] = 0.f;

        // -------- Wc = W1 @ W2: one warp per W1 row; sW2 aliased onto dyn ---
        float* sW2 = dyn;                       // [Cc][Hh] row-major (8KB)
        for (int i = tid; i < Hh * Cc; i += TPB)
            sW2[(i & 3) * Hh + (i >> 2)] = W2[i];
        __syncthreads();

        const int d    = blk * 8 + (tid >> 5);
        const int lane = tid & 31;
        const float* row = W1 + (long long)d * Hh;

        float a0 = 0.f, a1 = 0.f, a2 = 0.f, a3 = 0.f;
        for (int j = lane; j < Hh; j += 32) {
            const float wv = row[j];
            a0 += wv * sW2[0 * Hh + j]; a1 += wv * sW2[1 * Hh + j];
            a2 += wv * sW2[2 * Hh + j]; a3 += wv * sW2[3 * Hh + j];
        }
        #pragma unroll
        for (int o = 16; o > 0; o >>= 1) {
            a0 += __shfl_xor_sync(0xffffffffu, a0, o);
            a1 += __shfl_xor_sync(0xffffffffu, a1, o);
            a2 += __shfl_xor_sync(0xffffffffu, a2, o);
            a3 += __shfl_xor_sync(0xffffffffu, a3, o);
        }
        if (lane == 0)
            reinterpret_cast<float4*>(g_Wc)[d] = make_float4(a0, a1, a2, a3);
        return;
    }

    // ---------------- pass1 ------------------------------------------------
    const int c = blk - WCB;                    // chunk id (b*Ss + s)
    __shared__ __align__(16) float sd[2][TR][8];  // double-buffered score table

    const float4 q = reinterpret_cast<const float4*>(query)[tid];

    float4 acc = make_float4(0.f, 0.f, 0.f, 0.f);
    float4 sum = make_float4(0.f, 0.f, 0.f, 0.f);
    float4 mxv = make_float4(-1e30f, -1e30f, -1e30f, -1e30f);
    float  m = -1e30f, l = 0.f;

    const float* base = bags + (long long)c * (ROWS * Dd);   // contiguous chunk
    const uint32_t sbase = (uint32_t)__cvta_generic_to_shared(dyn)
                         + (uint32_t)(tid * 16);             // own slot column
    const int w = tid >> 5, lane = tid & 31;

    // prologue: fill the ring (tiles 0..STAGES-1, one commit group each)
    #pragma unroll
    for (int t = 0; t < STAGES; t++) {
        #pragma unroll
        for (int r = 0; r < TR; r++)
            cp16(sbase + (uint32_t)((t * TR + r) * Dd * 4),
                 base + (long long)(t * TR + r) * Dd + tid * 4);
        cp_commit();
    }

    for (int t = 0; t < NT; t++) {
        const int buf = t & (STAGES - 1);
        const int sb2 = t & 1;
        cp_wait<STAGES - 1>();                  // own tile-t slots complete

        // read own 16B slots (thread-private: no barrier needed)
        const float* sb = dyn + buf * (TR * Dd) + tid * 4;
        const float4 x0 = *reinterpret_cast<const float4*>(sb);
        const float4 x1 = *reinterpret_cast<const float4*>(sb + Dd);

        float p0 = x0.x * q.x + x0.y * q.y + x0.z * q.z + x0.w * q.w;
        float p1 = x1.x * q.x + x1.y * q.y + x1.z * q.z + x1.w * q.w;
        #pragma unroll
        for (int o = 16; o > 0; o >>= 1) {
            p0 += __shfl_xor_sync(0xffffffffu, p0, o);
            p1 += __shfl_xor_sync(0xffffffffu, p1, o);
        }
        if (lane == 0) { sd[sb2][0][w] = p0; sd[sb2][1][w] = p1; }

        // refill own slots with tile t+STAGES (no WAR: slots thread-private)
        const int ft = t + STAGES;
        if (ft < NT) {
            #pragma unroll
            for (int r = 0; r < TR; r++)
                cp16(sbase + (uint32_t)((buf * TR + r) * Dd * 4),
                     base + (long long)(ft * TR + r) * Dd + tid * 4);
        }
        cp_commit();                            // commit (possibly empty) group

        __syncthreads();                        // sd[sb2] ready (only sync!)

        const float4 a0 = *reinterpret_cast<const float4*>(&sd[sb2][0][0]);
        const float4 b0 = *reinterpret_cast<const float4*>(&sd[sb2][0][4]);
        const float4 a1 = *reinterpret_cast<const float4*>(&sd[sb2][1][0]);
        const float4 b1 = *reinterpret_cast<const float4*>(&sd[sb2][1][4]);
        const float sc0 = ((a0.x + a0.y) + (a0.z + a0.w))
                        + ((b0.x + b0.y) + (b0.z + b0.w));
        const float sc1 = ((a1.x + a1.y) + (a1.z + a1.w))
                        + ((b1.x + b1.y) + (b1.z + b1.w));

        // batch-max online softmax: one rescale per tile
        const float mn   = fmaxf(m, fmaxf(sc0, sc1));
        const float corr = __expf(m - mn);
        const float e0   = __expf(sc0 - mn);
        const float e1   = __expf(sc1 - mn);

        l = l * corr + e0 + e1;
        acc.x = (acc.x * corr + e0 * x0.x) + e1 * x1.x;
        acc.y = (acc.y * corr + e0 * x0.y) + e1 * x1.y;
        acc.z = (acc.z * corr + e0 * x0.z) + e1 * x1.z;
        acc.w = (acc.w * corr + e0 * x0.w) + e1 * x1.w;
        sum.x += x0.x + x1.x; sum.y += x0.y + x1.y;
        sum.z += x0.z + x1.z; sum.w += x0.w + x1.w;
        mxv.x = fmaxf(mxv.x, fmaxf(x0.x, x1.x));
        mxv.y = fmaxf(mxv.y, fmaxf(x0.y, x1.y));
        mxv.z = fmaxf(mxv.z, fmaxf(x0.z, x1.z));
        mxv.w = fmaxf(mxv.w, fmaxf(x0.w, x1.w));
        m = mn;
    }

    reinterpret_cast<float4*>(g_Pacc[c])[tid] = acc;
    reinterpret_cast<float4*>(g_Psum[c])[tid] = sum;
    reinterpret_cast<float4*>(g_Pmx[c])[tid]  = mxv;
    if (tid == 0) { g_Pm[c] = m; g_Pl[c] = l; }
}

// ============================================================================
// K2: merge chunk partials + dot with Wc + atomic-accumulate into out.
//   grid = Bb*KSL (96) x 128 threads. block (b, j): sec = j>>1, 128 f4 slots.
//   out was zeroed by k1; each block adds its partial 4-vector (6 adds/slot).
// ============================================================================
__global__ __launch_bounds__(128) void k2_kernel(
    const float* __restrict__ b1, const float* __restrict__ W2,
    const float* __restrict__ b2, float* __restrict__ out)
{
    const int b   = blockIdx.x / KSL;
    const int j   = blockIdx.x % KSL;
    const int tid = threadIdx.x;
    const int sec = j >> 1;                 // uniform per block
    const int d4  = (j & 1) * 128 + tid;
    const int g0  = b * Ss;

    float4 v;
    if (sec == 0) {
        float4 a = make_float4(0.f, 0.f, 0.f, 0.f);
        #pragma unroll 16
        for (int s = 0; s < Ss; s++) {
            float4 u = reinterpret_cast<const float4*>(g_Psum[g0 + s])[d4];
            a.x += u.x; a.y += u.y; a.z += u.z; a.w += u.w;
        }
        const float invN = 1.f / (float)Nn;
        v = make_float4(a.x * invN, a.y * invN, a.z * invN, a.w * invN);
    } else if (sec == 1) {
        float4 a = make_float4(-1e30f, -1e30f, -1e30f, -1e30f);
        #pragma unroll 16
        for (int s = 0; s < Ss; s++) {
            float4 u = reinterpret_cast<const float4*>(g_Pmx[g0 + s])[d4];
            a.x = fmaxf(a.x, u.x); a.y = fmaxf(a.y, u.y);
            a.z = fmaxf(a.z, u.z); a.w = fmaxf(a.w, u.w);
        }
        v = a;
    } else {
        __shared__ float swe[Ss];
        float M = -1e30f;
        #pragma unroll
        for (int s = 0; s < Ss; s++) M = fmaxf(M, g_Pm[g0 + s]);  // L1-broadcast
        if (tid < Ss) swe[tid] = __expf(g_Pm[g0 + tid] - M);
        __syncthreads();
        float L = 0.f;
        #pragma unroll
        for (int s = 0; s < Ss; s++) L += g_Pl[g0 + s] * swe[s];
        float4 a = make_float4(0.f, 0.f, 0.f, 0.f);
        #pragma unroll 16
        for (int s = 0; s < Ss; s++) {
            const float we = swe[s];
            float4 u = reinterpret_cast<const float4*>(g_Pacc[g0 + s])[d4];
            a.x += u.x * we; a.y += u.y * we; a.z += u.z * we; a.w += u.w * we;
        }
        const float invL = 1.f / L;
        v = make_float4(a.x * invL, a.y * invL, a.z * invL, a.w * invL);
    }

    // dot with 4 Wc rows for this thread's 4 d-slots
    const int    rbase = sec * Dd + d4 * 4;
    const float4 w0 = reinterpret_cast<const float4*>(g_Wc)[rbase + 0];
    const float4 w1 = reinterpret_cast<const float4*>(g_Wc)[rbase + 1];
    const float4 w2 = reinterpret_cast<const float4*>(g_Wc)[rbase + 2];
    const float4 w3 = reinterpret_cast<const float4*>(g_Wc)[rbase + 3];
    float o0 = v.x * w0.x + v.y * w1.x + v.z * w2.x + v.w * w3.x;
    float o1 = v.x * w0.y + v.y * w1.y + v.z * w2.y + v.w * w3.y;
    float o2 = v.x * w0.z + v.y * w1.z + v.z * w2.z + v.w * w3.z;
    float o3 = v.x * w0.w + v.y * w1.w + v.z * w2.w + v.w * w3.w;

    // block (b,0) additionally folds the bias terms b1 @ W2 and b2
    if (j == 0) {
        #pragma unroll
        for (int k = 0; k < 4; k++) {
            const int jj = tid * 4 + k;
            const float  bv = b1[jj];
            const float4 wr = reinterpret_cast<const float4*>(W2)[jj];
            o0 += bv * wr.x; o1 += bv * wr.y; o2 += bv * wr.z; o3 += bv * wr.w;
        }
    }

    // block reduction, then one atomicAdd per class
    #pragma unroll
    for (int o = 16; o > 0; o >>= 1) {
        o0 += __shfl_xor_sync(0xffffffffu, o0, o);
        o1 += __shfl_xor_sync(0xffffffffu, o1, o);
        o2 += __shfl_xor_sync(0xffffffffu, o2, o);
        o3 += __shfl_xor_sync(0xffffffffu, o3, o);
    }
    __shared__ float red[4][4];
    const int w = tid >> 5, lane = tid & 31;
    if (lane == 0) { red[w][0] = o0; red[w][1] = o1; red[w][2] = o2; red[w][3] = o3; }
    __syncthreads();
    if (tid < 4) {
        float t = red[0][tid] + red[1][tid] + red[2][tid] + red[3][tid];
        if (j == 0) t += b2[tid];
        atomicAdd(&out[b * 4 + tid], t);
    }
}

// ---------------- launcher --------------------------------------------------
extern "C" void kernel_launch(void* const* d_in, const int* in_sizes, int n_in,
                              void* d_out, int out_size)
{
    const float* bags  = (const float*)d_in[0];   // [16, 4096, 1024]
    const float* query = (const float*)d_in[1];   // [1024]
    const float* W1    = (const float*)d_in[2];   // [3072, 512]
    const float* b1    = (const float*)d_in[3];   // [512]
    const float* W2    = (const float*)d_in[4];   // [512, 4]
    const float* b2    = (const float*)d_in[5];   // [4]
    float*       out   = (float*)d_out;           // [16, 4]

    const int dynBytes = STAGES * TR * Dd * sizeof(float);   // 32768 B
    k1_kernel<<<WCB + NCH, TPB, dynBytes>>>(bags, query, W1, W2, out);
    k2_kernel<<<Bb * KSL, 128>>>(b1, W2, b2, out);
}

// round 11
// speedup vs baseline: 1.2099x; 1.2099x over previous
#include <cuda_runtime.h>
#include <cstdint>

// Problem constants
#define Bb   16
#define Nn   4096
#define Dd   1024
#define Hh   512
#define Cc   4
#define Ss   64                  // chunks per bag
#define ROWS 64                  // rows per chunk (Nn/Ss)
#define TPB  256
#define NCH  (Bb * Ss)           // 1024 chunk CTAs
#define WCB  384                 // Wc CTAs (8 W1-rows each) -- run FIRST
#define TR   2                   // rows per tile
#define NT   (ROWS / TR)         // 32 tiles per chunk
#define STAGES 4                 // ring depth: 4 x 8KB = 32KB dyn smem
#define STG_B  (TR * Dd * 4)     // stage stride bytes (8192)

// ---------------- scratch (static device arrays; no cudaMalloc) -------------
__device__ float g_Pm[NCH];
__device__ float g_Pl[NCH];
__device__ float g_Pacc[NCH][Dd];
__device__ float g_Psum[NCH][Dd];
__device__ float g_Pmx[NCH][Dd];
__device__ float g_Wc[3 * Dd][Cc];     // W1 @ W2 (head is affine: no activation)

__device__ __forceinline__ void cp16(uint32_t smem_dst, const float* gsrc) {
    asm volatile("cp.async.cg.shared.global [%0], [%1], 16;\n"
                 :: "r"(smem_dst), "l"(gsrc));
}
__device__ __forceinline__ void cp_commit() {
    asm volatile("cp.async.commit_group;\n");
}
template <int N> __device__ __forceinline__ void cp_wait() {
    asm volatile("cp.async.wait_group %0;\n" :: "n"(N));
}
// warp-wide fp32 add-reduce via shfl butterfly (sm_103a has no redux.f32)
__device__ __forceinline__ float warp_sum(float v) {
    #pragma unroll
    for (int o = 16; o > 0; o >>= 1)
        v += __shfl_xor_sync(0xffffffffu, v, o);
    return v;
}

// ============================================================================
// K1: fused [Wc = W1 @ W2] (blocks 0..WCB) + [pass1 pooling] (blocks WCB..)
//   pass1: thread-private cp.async ring slots (no visibility barrier needed);
//   score reduce = shfl butterfly + lane0 shared-atomicAdd into a 4-phase
//   rotated score buffer; ONE __syncthreads per 2-row tile.
// ============================================================================
extern __shared__ float dyn[];   // [STAGES][TR][Dd] = 32768 B (pass1) / sW2 (Wc)

__global__ __launch_bounds__(TPB, 4) void k1_kernel(
    const float* __restrict__ bags, const float* __restrict__ query,
    const float* __restrict__ W1,   const float* __restrict__ W2,
    float* __restrict__ out)
{
    const int blk = blockIdx.x;
    const int tid = threadIdx.x;

    if (blk < WCB) {
        // block 0 also zero-inits out (k2 accumulates into it atomically)
        if (blk == 0 && tid < Bb * Cc) out[tid] = 0.f;

        // -------- Wc = W1 @ W2: one warp per W1 row; sW2 aliased onto dyn ---
        float* sW2 = dyn;                       // [Cc][Hh] row-major (8KB)
        for (int i = tid; i < Hh * Cc; i += TPB)
            sW2[(i & 3) * Hh + (i >> 2)] = W2[i];
        __syncthreads();

        const int d    = blk * 8 + (tid >> 5);
        const int lane = tid & 31;
        const float* row = W1 + (long long)d * Hh;

        float a0 = 0.f, a1 = 0.f, a2 = 0.f, a3 = 0.f;
        for (int j = lane; j < Hh; j += 32) {
            const float wv = row[j];
            a0 += wv * sW2[0 * Hh + j]; a1 += wv * sW2[1 * Hh + j];
            a2 += wv * sW2[2 * Hh + j]; a3 += wv * sW2[3 * Hh + j];
        }
        a0 = warp_sum(a0); a1 = warp_sum(a1);
        a2 = warp_sum(a2); a3 = warp_sum(a3);
        if (lane == 0)
            reinterpret_cast<float4*>(g_Wc)[d] = make_float4(a0, a1, a2, a3);
        return;
    }

    // ---------------- pass1 ------------------------------------------------
    const int c = blk - WCB;                    // chunk id (b*Ss + s)
    __shared__ float s_sc[4][2];                // 4-phase rotated score pair

    if (tid < 8) ((float*)s_sc)[tid] = 0.f;     // init all phases

    const float4 q = reinterpret_cast<const float4*>(query)[tid];

    float4 acc = make_float4(0.f, 0.f, 0.f, 0.f);
    float4 sum = make_float4(0.f, 0.f, 0.f, 0.f);
    float4 mxv = make_float4(-1e30f, -1e30f, -1e30f, -1e30f);
    float  m = -1e30f, l = 0.f;

    const uint32_t sbase = (uint32_t)__cvta_generic_to_shared(dyn)
                         + (uint32_t)(tid * 16);   // own slot column
    const int lane = tid & 31;

    // fetch pointer (strength-reduced): advances TR*Dd per issued tile
    const float* gf = bags + (long long)c * (ROWS * Dd) + tid * 4;

    __syncthreads();                            // s_sc init visible

    // prologue: fill the ring (tiles 0..3)
    #pragma unroll
    for (int t = 0; t < STAGES; t++) {
        cp16(sbase + (uint32_t)(t * STG_B), gf);
        cp16(sbase + (uint32_t)(t * STG_B) + (uint32_t)(Dd * 4), gf + Dd);
        cp_commit();
        gf += TR * Dd;
    }

    for (int t = 0; t < NT; t++) {
        const int buf = t & (STAGES - 1);
        cp_wait<STAGES - 1>();                  // own tile-t slots complete

        // read own 16B slots (thread-private: no barrier needed)
        const float* sb = dyn + buf * (TR * Dd) + tid * 4;
        const float4 x0 = *reinterpret_cast<const float4*>(sb);
        const float4 x1 = *reinterpret_cast<const float4*>(sb + Dd);

        float p0 = x0.x * q.x + x0.y * q.y + x0.z * q.z + x0.w * q.w;
        float p1 = x1.x * q.x + x1.y * q.y + x1.z * q.z + x1.w * q.w;
        p0 = warp_sum(p0);
        p1 = warp_sum(p1);
        if (lane == 0) {                        // cross-warp: shared atomics
            atomicAdd(&s_sc[t & 3][0], p0);
            atomicAdd(&s_sc[t & 3][1], p1);
        }

        // refill own slots with tile t+STAGES (no WAR: slots thread-private)
        if (t + STAGES < NT) {
            cp16(sbase + (uint32_t)(buf * STG_B), gf);
            cp16(sbase + (uint32_t)(buf * STG_B) + (uint32_t)(Dd * 4), gf + Dd);
            gf += TR * Dd;
        }
        cp_commit();                            // commit (possibly empty) group

        // reset phase t+2 for its next use. Safe: phase p's readers finished
        // before barrier(p-3); this reset runs after barrier(p-3).
        if (tid == 0) {
            s_sc[(t + 2) & 3][0] = 0.f;
            s_sc[(t + 2) & 3][1] = 0.f;
        }

        __syncthreads();                        // scores ready (only sync!)

        const float sc0 = s_sc[t & 3][0];
        const float sc1 = s_sc[t & 3][1];

        // batch-max online softmax: one rescale per tile
        const float mn   = fmaxf(m, fmaxf(sc0, sc1));
        const float corr = __expf(m - mn);
        const float e0   = __expf(sc0 - mn);
        const float e1   = __expf(sc1 - mn);

        l = l * corr + e0 + e1;
        acc.x = (acc.x * corr + e0 * x0.x) + e1 * x1.x;
        acc.y = (acc.y * corr + e0 * x0.y) + e1 * x1.y;
        acc.z = (acc.z * corr + e0 * x0.z) + e1 * x1.z;
        acc.w = (acc.w * corr + e0 * x0.w) + e1 * x1.w;
        sum.x += x0.x + x1.x; sum.y += x0.y + x1.y;
        sum.z += x0.z + x1.z; sum.w += x0.w + x1.w;
        mxv.x = fmaxf(mxv.x, fmaxf(x0.x, x1.x));
        mxv.y = fmaxf(mxv.y, fmaxf(x0.y, x1.y));
        mxv.z = fmaxf(mxv.z, fmaxf(x0.z, x1.z));
        mxv.w = fmaxf(mxv.w, fmaxf(x0.w, x1.w));
        m = mn;
    }

    reinterpret_cast<float4*>(g_Pacc[c])[tid] = acc;
    reinterpret_cast<float4*>(g_Psum[c])[tid] = sum;
    reinterpret_cast<float4*>(g_Pmx[c])[tid]  = mxv;
    if (tid == 0) { g_Pm[c] = m; g_Pl[c] = l; }
}

// ============================================================================
// K2: merge chunk partials + dot with Wc + atomic-accumulate into out.
//   grid = 96 blocks (b x sec x half), 1024 threads = 8 chunk-groups x 128
//   float4 slots. 8x the parallelism of the old k2, unroll-8 load streams.
// ============================================================================
#define K2T 1024
__global__ __launch_bounds__(K2T) void k2_kernel(
    const float* __restrict__ b1, const float* __restrict__ W2,
    const float* __restrict__ b2, float* __restrict__ out)
{
    const int blk = blockIdx.x;
    const int b   = blk / 6;
    const int j   = blk % 6;
    const int sec = j >> 1;                 // 0 mean, 1 max, 2 attn (uniform)
    const int h   = j & 1;
    const int tid = threadIdx.x;
    const int slot = tid & 127;
    const int cg   = tid >> 7;              // chunk-group 0..7
    const int d4   = h * 128 + slot;
    const int g0   = b * Ss;

    __shared__ float  swe[Ss];
    __shared__ float4 sred[8][128];         // 16 KB cross-cg buffer

    float4 a;
    if (sec == 0) {
        a = make_float4(0.f, 0.f, 0.f, 0.f);
        #pragma unroll
        for (int k = 0; k < 8; k++) {
            float4 u = reinterpret_cast<const float4*>(g_Psum[g0 + cg * 8 + k])[d4];
            a.x += u.x; a.y += u.y; a.z += u.z; a.w += u.w;
        }
    } else if (sec == 1) {
        a = make_float4(-1e30f, -1e30f, -1e30f, -1e30f);
        #pragma unroll
        for (int k = 0; k < 8; k++) {
            float4 u = reinterpret_cast<const float4*>(g_Pmx[g0 + cg * 8 + k])[d4];
            a.x = fmaxf(a.x, u.x); a.y = fmaxf(a.y, u.y);
            a.z = fmaxf(a.z, u.z); a.w = fmaxf(a.w, u.w);
        }
    } else {
        float M = -1e30f;
        #pragma unroll
        for (int s = 0; s < Ss; s++) M = fmaxf(M, g_Pm[g0 + s]);  // broadcast
        if (tid < Ss) swe[tid] = __expf(g_Pm[g0 + tid] - M);
        __syncthreads();
        a = make_float4(0.f, 0.f, 0.f, 0.f);
        #pragma unroll
        for (int k = 0; k < 8; k++) {
            const float we = swe[cg * 8 + k];
            float4 u = reinterpret_cast<const float4*>(g_Pacc[g0 + cg * 8 + k])[d4];
            a.x += u.x * we; a.y += u.y * we; a.z += u.z * we; a.w += u.w * we;
        }
    }
    sred[cg][slot] = a;
    __syncthreads();

    float o0 = 0.f, o1 = 0.f, o2 = 0.f, o3 = 0.f;
    if (tid < 128) {
        float4 v;
        if (sec == 1) {
            v = make_float4(-1e30f, -1e30f, -1e30f, -1e30f);
            #pragma unroll
            for (int g = 0; g < 8; g++) {
                float4 u = sred[g][tid];
                v.x = fmaxf(v.x, u.x); v.y = fmaxf(v.y, u.y);
                v.z = fmaxf(v.z, u.z); v.w = fmaxf(v.w, u.w);
            }
        } else {
            v = make_float4(0.f, 0.f, 0.f, 0.f);
            #pragma unroll
            for (int g = 0; g < 8; g++) {
                float4 u = sred[g][tid];
                v.x += u.x; v.y += u.y; v.z += u.z; v.w += u.w;
            }
            if (sec == 0) {
                const float invN = 1.f / (float)Nn;
                v.x *= invN; v.y *= invN; v.z *= invN; v.w *= invN;
            } else {
                float L = 0.f;
                #pragma unroll
                for (int s = 0; s < Ss; s++) L += g_Pl[g0 + s] * swe[s];
                const float invL = 1.f / L;
                v.x *= invL; v.y *= invL; v.z *= invL; v.w *= invL;
            }
        }

        const int dd4 = h * 128 + tid;
        const int rbase = sec * Dd + dd4 * 4;
        const float4 w0 = reinterpret_cast<const float4*>(g_Wc)[rbase + 0];
        const float4 w1 = reinterpret_cast<const float4*>(g_Wc)[rbase + 1];
        const float4 w2 = reinterpret_cast<const float4*>(g_Wc)[rbase + 2];
        const float4 w3 = reinterpret_cast<const float4*>(g_Wc)[rbase + 3];
        o0 = v.x * w0.x + v.y * w1.x + v.z * w2.x + v.w * w3.x;
        o1 = v.x * w0.y + v.y * w1.y + v.z * w2.y + v.w * w3.y;
        o2 = v.x * w0.z + v.y * w1.z + v.z * w2.z + v.w * w3.z;
        o3 = v.x * w0.w + v.y * w1.w + v.z * w2.w + v.w * w3.w;

        // block (b,0) folds the bias term b1 @ W2 (4 rows per thread)
        if (j == 0) {
            #pragma unroll
            for (int k = 0; k < 4; k++) {
                const int jj = tid * 4 + k;
                const float  bv = b1[jj];
                const float4 wr = reinterpret_cast<const float4*>(W2)[jj];
                o0 += bv * wr.x; o1 += bv * wr.y; o2 += bv * wr.z; o3 += bv * wr.w;
            }
        }
    }

    // reduce the 4 contributing warps, then one atomicAdd per class
    o0 = warp_sum(o0); o1 = warp_sum(o1);
    o2 = warp_sum(o2); o3 = warp_sum(o3);
    __shared__ float red[4][4];
    const int w = tid >> 5, lane = tid & 31;
    if (w < 4 && lane == 0) { red[w][0] = o0; red[w][1] = o1; red[w][2] = o2; red[w][3] = o3; }
    __syncthreads();
    if (tid < 4) {
        float t = red[0][tid] + red[1][tid] + red[2][tid] + red[3][tid];
        if (j == 0) t += b2[tid];
        atomicAdd(&out[b * 4 + tid], t);
    }
}

// ---------------- launcher --------------------------------------------------
extern "C" void kernel_launch(void* const* d_in, const int* in_sizes, int n_in,
                              void* d_out, int out_size)
{
    const float* bags  = (const float*)d_in[0];   // [16, 4096, 1024]
    const float* query = (const float*)d_in[1];   // [1024]
    const float* W1    = (const float*)d_in[2];   // [3072, 512]
    const float* b1    = (const float*)d_in[3];   // [512]
    const float* W2    = (const float*)d_in[4];   // [512, 4]
    const float* b2    = (const float*)d_in[5];   // [4]
    float*       out   = (float*)d_out;           // [16, 4]

    const int dynBytes = STAGES * TR * Dd * sizeof(float);   // 32768 B
    k1_kernel<<<WCB + NCH, TPB, dynBytes>>>(bags, query, W1, W2, out);
    k2_kernel<<<Bb * 6, K2T>>>(b1, W2, b2, out);
}